// round 9
// baseline (speedup 1.0000x reference)
#include <cuda_runtime.h>
#include <cuda_bf16.h>
#include <cstdint>

// Problem constants
#define B_  32
#define S_  256
#define D_  17
#define M_  512
#define H_  8
#define DK_ 64
#define NROW  139264          // B*S*D rows of width 512
#define NSAMP 8192            // B*S

// ---------------------------------------------------------------------------
// Scratch (__device__ globals; allocation-free rule)
// ---------------------------------------------------------------------------
__device__ float g_q[(size_t)NROW * M_];
__device__ float g_k[(size_t)NROW * M_];
__device__ float g_v[(size_t)NROW * M_];
__device__ __nv_bfloat16 g_xh[(size_t)NROW * M_];
__device__ __nv_bfloat16 g_xl[(size_t)NROW * M_];
__device__ __nv_bfloat16 g_ch[(size_t)NROW * M_];
__device__ __nv_bfloat16 g_cl[(size_t)NROW * M_];
__device__ __nv_bfloat16 g_wh[4 * 512 * 512];   // Wq,Wk,Wv,Wo hi (rows contiguous)
__device__ __nv_bfloat16 g_wl[4 * 512 * 512];   // lo

// ---------------------------------------------------------------------------
// Helpers
// ---------------------------------------------------------------------------
__device__ __forceinline__ uint32_t smem_u32(const void* p) {
    uint32_t a;
    asm("{ .reg .u64 t; cvta.to.shared.u64 t, %1; cvt.u32.u64 %0, t; }"
        : "=r"(a) : "l"(p));
    return a;
}

__device__ __forceinline__ void cp16(uint32_t dst, const void* src) {
    asm volatile("cp.async.cg.shared.global [%0], [%1], 16;" :: "r"(dst), "l"(src));
}

__device__ __forceinline__ void ldmx4(uint32_t* r, uint32_t addr) {
    asm volatile("ldmatrix.sync.aligned.m8n8.x4.shared.b16 {%0,%1,%2,%3}, [%4];"
                 : "=r"(r[0]), "=r"(r[1]), "=r"(r[2]), "=r"(r[3]) : "r"(addr));
}

__device__ __forceinline__ void mma16816(float* d, const uint32_t* a,
                                         uint32_t b0, uint32_t b1) {
    asm volatile(
        "mma.sync.aligned.m16n8k16.row.col.f32.bf16.bf16.f32 "
        "{%0,%1,%2,%3}, {%4,%5,%6,%7}, {%8,%9}, {%0,%1,%2,%3};"
        : "+f"(d[0]), "+f"(d[1]), "+f"(d[2]), "+f"(d[3])
        : "r"(a[0]), "r"(a[1]), "r"(a[2]), "r"(a[3]), "r"(b0), "r"(b1));
}

// ---------------------------------------------------------------------------
// bf16-split GEMM on HMMA, fused-phase structure (R6 best, unchanged):
//   pass A (iters 0-7):  acc += xh.Wh + xh.Wl   (A LDSM shared by both B's)
//   pass B (iters 8-15): acc += xl.Wh
// BM=BN=128, BK=64 per iter, 128 threads (4 warps 2x2), warp tile 64x64.
// ---------------------------------------------------------------------------
#define ITERS 16
#define ROWB 144
#define STAGE_BYTES (384 * ROWB)    // A(128) + B0(128) + B1(128) rows

__device__ __forceinline__ void load_iter(
    int tid, uint32_t sbase, int r0, int c0, int it,
    const __nv_bfloat16* __restrict__ xh, const __nv_bfloat16* __restrict__ xl,
    const __nv_bfloat16* __restrict__ Wh, const __nv_bfloat16* __restrict__ Wl)
{
    const int kk = (it & 7) * 64;
    const __nv_bfloat16* A = (it < 8) ? xh : xl;
    #pragma unroll
    for (int t = 0; t < 8; t++) {                 // A: 128 rows x 128B
        int f = tid + t * 128;
        int row = f >> 3, ch = f & 7;
        cp16(sbase + row * ROWB + ch * 16, A + ((size_t)(r0 + row) << 9) + kk + ch * 8);
    }
    const uint32_t b0 = sbase + 128 * ROWB;
    #pragma unroll
    for (int t = 0; t < 8; t++) {                 // B0 = Wh
        int f = tid + t * 128;
        int row = f >> 3, ch = f & 7;
        cp16(b0 + row * ROWB + ch * 16, Wh + ((size_t)(c0 + row) << 9) + kk + ch * 8);
    }
    if (it < 8) {
        const uint32_t b1 = sbase + 256 * ROWB;
        #pragma unroll
        for (int t = 0; t < 8; t++) {             // B1 = Wl (pass A only)
            int f = tid + t * 128;
            int row = f >> 3, ch = f & 7;
            cp16(b1 + row * ROWB + ch * 16, Wl + ((size_t)(c0 + row) << 9) + kk + ch * 8);
        }
    }
    asm volatile("cp.async.commit_group;");
}

template<int MODE>
__global__ __launch_bounds__(128)
void gemm_mma(const __nv_bfloat16* __restrict__ Ah,
              const __nv_bfloat16* __restrict__ Al,
              const __nv_bfloat16* __restrict__ Wh,
              const __nv_bfloat16* __restrict__ Wl,
              float* __restrict__ C0, float* __restrict__ C1,
              float* __restrict__ C2,
              const float* __restrict__ bias,
              const float* __restrict__ resid)
{
    extern __shared__ __align__(128) char smem[];

    const int tid = threadIdx.x;
    const int wid = tid >> 5;
    const int lid = tid & 31;
    const int c0 = blockIdx.x << 7;    // col tile (fast dim -> A L2 reuse)
    const int r0 = blockIdx.y << 7;
    const int m0 = (wid & 1) * 64;
    const int n0 = (wid >> 1) * 64;
    const uint32_t sb = smem_u32(smem);

    float acc[4][8][4];
    #pragma unroll
    for (int i = 0; i < 4; i++)
        #pragma unroll
        for (int j = 0; j < 8; j++)
            #pragma unroll
            for (int q = 0; q < 4; q++) acc[i][j][q] = 0.f;

    load_iter(tid, sb, r0, c0, 0, Ah, Al, Wh, Wl);

    const uint32_t a_off = (uint32_t)((m0 + (lid & 15)) * ROWB + ((lid >> 4) << 4));
    const uint32_t b_off = (uint32_t)((n0 + (lid & 7) + ((lid >> 4) << 3)) * ROWB
                                      + (((lid >> 3) & 1) << 4));

    for (int it = 0; it < ITERS; it++) {
        asm volatile("cp.async.wait_group 0;");
        __syncthreads();

        if (it + 1 < ITERS)
            load_iter(tid, sb + ((it + 1) & 1) * STAGE_BYTES, r0, c0, it + 1,
                      Ah, Al, Wh, Wl);

        const uint32_t as  = sb + (it & 1) * STAGE_BYTES;
        const uint32_t bs0 = as + 128 * ROWB;
        const uint32_t bs1 = as + 256 * ROWB;

        #pragma unroll
        for (int kt = 0; kt < 4; kt++) {
            uint32_t a[4][4], b[4][4];
            #pragma unroll
            for (int mi = 0; mi < 4; mi++)
                ldmx4(a[mi], as + a_off + (uint32_t)(mi * 16 * ROWB + kt * 32));
            #pragma unroll
            for (int nj = 0; nj < 4; nj++)
                ldmx4(b[nj], bs0 + b_off + (uint32_t)(nj * 16 * ROWB + kt * 32));
            #pragma unroll
            for (int mi = 0; mi < 4; mi++)
                #pragma unroll
                for (int ni = 0; ni < 8; ni++)
                    mma16816(acc[mi][ni], a[mi],
                             b[ni >> 1][(ni & 1) * 2], b[ni >> 1][(ni & 1) * 2 + 1]);
            if (it < 8) {   // pass A: second B tile (Wl), reuse A fragments
                #pragma unroll
                for (int nj = 0; nj < 4; nj++)
                    ldmx4(b[nj], bs1 + b_off + (uint32_t)(nj * 16 * ROWB + kt * 32));
                #pragma unroll
                for (int mi = 0; mi < 4; mi++)
                    #pragma unroll
                    for (int ni = 0; ni < 8; ni++)
                        mma16816(acc[mi][ni], a[mi],
                                 b[ni >> 1][(ni & 1) * 2], b[ni >> 1][(ni & 1) * 2 + 1]);
            }
        }
    }

    // Epilogue
    float* C;
    int col0;
    if (MODE == 0) {
        const int which = c0 >> 9;
        C = (which == 0) ? C0 : (which == 1) ? C1 : C2;
        col0 = c0 & 511;
    } else {
        C = C0;
        col0 = c0;
    }
    const int g  = lid >> 2;
    const int tg = lid & 3;
    #pragma unroll
    for (int mi = 0; mi < 4; mi++) {
        #pragma unroll
        for (int ni = 0; ni < 8; ni++) {
            const int r = r0 + m0 + mi * 16 + g;
            const int c = col0 + n0 + ni * 8 + tg * 2;
            float2 v0 = make_float2(acc[mi][ni][0], acc[mi][ni][1]);
            float2 v1 = make_float2(acc[mi][ni][2], acc[mi][ni][3]);
            if (MODE == 1) {
                const float2 bb = *(const float2*)(bias + c);
                const float2 q0 = *(const float2*)(resid + ((size_t)r << 9) + c);
                const float2 q1 = *(const float2*)(resid + ((size_t)(r + 8) << 9) + c);
                v0.x += bb.x + q0.x; v0.y += bb.y + q0.y;
                v1.x += bb.x + q1.x; v1.y += bb.y + q1.y;
            }
            *(float2*)(C + ((size_t)r << 9) + c)       = v0;
            *(float2*)(C + ((size_t)(r + 8) << 9) + c) = v1;
        }
    }
}

// ---------------------------------------------------------------------------
// fp32 -> (bf16 hi, bf16 lo) splits
// ---------------------------------------------------------------------------
__global__ __launch_bounds__(256)
void wsplit_kernel(const float* __restrict__ Wq, const float* __restrict__ Wk,
                   const float* __restrict__ Wv, const float* __restrict__ Wo,
                   __nv_bfloat16* __restrict__ hi, __nv_bfloat16* __restrict__ lo)
{
    const int w = blockIdx.y;
    const float* src = (w == 0) ? Wq : (w == 1) ? Wk : (w == 2) ? Wv : Wo;
    const int i = blockIdx.x * 256 + threadIdx.x;      // < 65536
    float4 v = ((const float4*)src)[i];
    __nv_bfloat16 h0 = __float2bfloat16(v.x);
    __nv_bfloat16 h1 = __float2bfloat16(v.y);
    __nv_bfloat16 h2 = __float2bfloat16(v.z);
    __nv_bfloat16 h3 = __float2bfloat16(v.w);
    __nv_bfloat162* hp = (__nv_bfloat162*)(hi + (size_t)w * 262144);
    __nv_bfloat162* lp = (__nv_bfloat162*)(lo + (size_t)w * 262144);
    hp[2 * i]     = __nv_bfloat162(h0, h1);
    hp[2 * i + 1] = __nv_bfloat162(h2, h3);
    lp[2 * i]     = __nv_bfloat162(__float2bfloat16(v.x - __bfloat162float(h0)),
                                   __float2bfloat16(v.y - __bfloat162float(h1)));
    lp[2 * i + 1] = __nv_bfloat162(__float2bfloat16(v.z - __bfloat162float(h2)),
                                   __float2bfloat16(v.w - __bfloat162float(h3)));
}

__global__ __launch_bounds__(256)
void split_kernel(const float* __restrict__ in, __nv_bfloat16* __restrict__ hi,
                  __nv_bfloat16* __restrict__ lo, int n4)
{
    int i = blockIdx.x * 256 + threadIdx.x;
    if (i >= n4) return;
    float4 v = ((const float4*)in)[i];
    __nv_bfloat16 h0 = __float2bfloat16(v.x);
    __nv_bfloat16 h1 = __float2bfloat16(v.y);
    __nv_bfloat16 h2 = __float2bfloat16(v.z);
    __nv_bfloat16 h3 = __float2bfloat16(v.w);
    __nv_bfloat162* hp = (__nv_bfloat162*)hi;
    __nv_bfloat162* lp = (__nv_bfloat162*)lo;
    hp[2 * i]     = __nv_bfloat162(h0, h1);
    hp[2 * i + 1] = __nv_bfloat162(h2, h3);
    lp[2 * i]     = __nv_bfloat162(__float2bfloat16(v.x - __bfloat162float(h0)),
                                   __float2bfloat16(v.y - __bfloat162float(h1)));
    lp[2 * i + 1] = __nv_bfloat162(__float2bfloat16(v.z - __bfloat162float(h2)),
                                   __float2bfloat16(v.w - __bfloat162float(h3)));
}

// ---------------------------------------------------------------------------
// Attention v4 (fixed sizes): smem-staged with buffer reuse:
//   BUF0 = q, then (after scores) v; BUF1 = k.
// Score/P regions keep stride 400/head. Score-block row bases are clamped to
// 13 so 4-row blocks cover rows 13..16 in-bounds (rows 13-15 recomputed, same
// values written twice -- idempotent). smem = 11248 floats = 45.0KB.
// One CTA per (sample, 4-head group), 128 threads, 4x4 register tiling.
// ---------------------------------------------------------------------------
#define AB0 0
#define AB1 4624
#define ASS 9248                 // 4 heads * 400
#define ASP 10848                // 400
__global__ __launch_bounds__(128)
void attn_kernel(const float* __restrict__ q, const float* __restrict__ k,
                 const float* __restrict__ v, const float* __restrict__ P,
                 __nv_bfloat16* __restrict__ ch, __nv_bfloat16* __restrict__ cl)
{
    __shared__ float sm[11248];  // 44992 bytes
    const int n  = blockIdx.x;
    const int hg = blockIdx.y;
    const int t  = threadIdx.x;
    const size_t base = (size_t)n * D_ * M_;

    // Phase 1: stage q -> BUF0, k -> BUF1 ([h][d][c], row stride 68)
    for (int f = t; f < 1088; f += 128) {
        int d = f >> 6, hc = f & 63;
        int h = hc >> 4, c4 = hc & 15;
        size_t goff = base + (size_t)d * 512 + (hg * 4 + h) * 64 + c4 * 4;
        int soff = (h * 17 + d) * 68 + c4 * 4;
        *(float4*)(sm + AB0 + soff) = *(const float4*)(q + goff);
        *(float4*)(sm + AB1 + soff) = *(const float4*)(k + goff);
    }
    for (int f = t; f < 289; f += 128)
        sm[ASP + (f / 17) * 20 + (f % 17)] = P[f];
    __syncthreads();

    // Phase 2: scores, 4 heads x 25 blocks of 4x4 = 100 tasks.
    // Block bases clamped to 13: last block covers rows/cols 13..16 (overlap
    // rows recompute identical values -> idempotent concurrent writes).
    if (t < 100) {
        const int h = t / 25, blk = t % 25;
        const int d0 = ((blk / 5) * 4 > 13) ? 13 : (blk / 5) * 4;
        const int e0 = ((blk % 5) * 4 > 13) ? 13 : (blk % 5) * 4;
        const float* sq = sm + AB0 + (h * 17 + d0) * 68;
        const float* sk = sm + AB1 + (h * 17 + e0) * 68;
        float acc[4][4];
        #pragma unroll
        for (int i = 0; i < 4; i++)
            #pragma unroll
            for (int j = 0; j < 4; j++) acc[i][j] = 0.f;
        #pragma unroll 4
        for (int c4 = 0; c4 < 16; c4++) {
            float4 qa[4], kb[4];
            #pragma unroll
            for (int i = 0; i < 4; i++) qa[i] = *(const float4*)(sq + i * 68 + c4 * 4);
            #pragma unroll
            for (int j = 0; j < 4; j++) kb[j] = *(const float4*)(sk + j * 68 + c4 * 4);
            #pragma unroll
            for (int i = 0; i < 4; i++)
                #pragma unroll
                for (int j = 0; j < 4; j++)
                    acc[i][j] += qa[i].x * kb[j].x + qa[i].y * kb[j].y
                               + qa[i].z * kb[j].z + qa[i].w * kb[j].w;
        }
        float* ss = sm + ASS + h * 400;
        #pragma unroll
        for (int i = 0; i < 4; i++)
            #pragma unroll
            for (int j = 0; j < 4; j++)
                ss[(d0 + i) * 20 + e0 + j] =
                    acc[i][j] * 0.125f + sm[ASP + (d0 + i) * 20 + e0 + j];
    }
    __syncthreads();

    // Phase 3: stage v into BUF0 (q no longer needed) + softmax on ss
    for (int f = t; f < 1088; f += 128) {
        int d = f >> 6, hc = f & 63;
        int h = hc >> 4, c4 = hc & 15;
        size_t goff = base + (size_t)d * 512 + (hg * 4 + h) * 64 + c4 * 4;
        *(float4*)(sm + AB0 + (h * 17 + d) * 68 + c4 * 4) = *(const float4*)(v + goff);
    }
    if (t < 68) {
        float* row = sm + ASS + (t / 17) * 400 + (t % 17) * 20;
        float mx = -1e30f;
        #pragma unroll
        for (int e = 0; e < 17; e++) mx = fmaxf(mx, row[e]);
        float sum = 0.f;
        #pragma unroll
        for (int e = 0; e < 17; e++) {
            float ex = __expf(row[e] - mx);
            row[e] = ex;
            sum += ex;
        }
        float inv = 1.f / sum;
        #pragma unroll
        for (int e = 0; e < 17; e++) row[e] *= inv;
    }
    __syncthreads();

    // Phase 4: ctx, 4 heads x (5 dblk x 16 cblk) = 320 tasks -> bf16 hi/lo.
    // Row base clamped to 13 (rows 13-15 recomputed identically; idempotent).
    for (int task = t; task < 320; task += 128) {
        const int h = task / 80, rem = task % 80;
        const int d0 = ((rem / 16) * 4 > 13) ? 13 : (rem / 16) * 4;
        const int c0c = (rem % 16) * 4;
        const float* ss = sm + ASS + h * 400;
        const float* sv = sm + AB0 + h * 17 * 68 + c0c;
        float acc[4][4];
        #pragma unroll
        for (int i = 0; i < 4; i++)
            #pragma unroll
            for (int j = 0; j < 4; j++) acc[i][j] = 0.f;
        #pragma unroll 1
        for (int e = 0; e < 17; e++) {
            const float4 vv = *(const float4*)(sv + e * 68);
            #pragma unroll
            for (int i = 0; i < 4; i++) {
                const float w = ss[(d0 + i) * 20 + e];
                acc[i][0] += w * vv.x;
                acc[i][1] += w * vv.y;
                acc[i][2] += w * vv.z;
                acc[i][3] += w * vv.w;
            }
        }
        #pragma unroll
        for (int i = 0; i < 4; i++) {
            const int d = d0 + i;
            const size_t off = base + (size_t)d * 512 + (hg * 4 + h) * 64 + c0c;
            __nv_bfloat16 hh[4], ll[4];
            #pragma unroll
            for (int j = 0; j < 4; j++) {
                hh[j] = __float2bfloat16(acc[i][j]);
                ll[j] = __float2bfloat16(acc[i][j] - __bfloat162float(hh[j]));
            }
            *(uint2*)(ch + off) = *(uint2*)hh;
            *(uint2*)(cl + off) = *(uint2*)ll;
        }
    }
}

// ---------------------------------------------------------------------------
// In-place LayerNorm (warp per row, width 512), eps = 1e-5
// ---------------------------------------------------------------------------
__global__ __launch_bounds__(256)
void ln_kernel(float* __restrict__ out, const float* __restrict__ gamma,
               const float* __restrict__ beta)
{
    const int row  = blockIdx.x * 8 + (threadIdx.x >> 5);
    const int lane = threadIdx.x & 31;
    const size_t base = (size_t)row * 512;

    float4 vals[4];
    float sum = 0.f, sq = 0.f;
    #pragma unroll
    for (int j = 0; j < 4; j++) {
        vals[j] = *(const float4*)(out + base + (size_t)(j * 32 + lane) * 4);
        sum += vals[j].x + vals[j].y + vals[j].z + vals[j].w;
        sq  += vals[j].x * vals[j].x + vals[j].y * vals[j].y
             + vals[j].z * vals[j].z + vals[j].w * vals[j].w;
    }
    #pragma unroll
    for (int o = 16; o > 0; o >>= 1) {
        sum += __shfl_xor_sync(0xffffffffu, sum, o);
        sq  += __shfl_xor_sync(0xffffffffu, sq,  o);
    }
    const float mean = sum * (1.f / 512.f);
    const float var  = sq * (1.f / 512.f) - mean * mean;
    const float rstd = rsqrtf(var + 1e-5f);

    #pragma unroll
    for (int j = 0; j < 4; j++) {
        int c = (j * 32 + lane) * 4;
        float4 g  = *(const float4*)(gamma + c);
        float4 bb = *(const float4*)(beta + c);
        float4 v;
        v.x = (vals[j].x - mean) * rstd * g.x + bb.x;
        v.y = (vals[j].y - mean) * rstd * g.y + bb.y;
        v.z = (vals[j].z - mean) * rstd * g.z + bb.z;
        v.w = (vals[j].w - mean) * rstd * g.w + bb.w;
        *(float4*)(out + base + c) = v;
    }
}

// ---------------------------------------------------------------------------
extern "C" void kernel_launch(void* const* d_in, const int* in_sizes, int n_in,
                              void* d_out, int out_size)
{
    const float* x     = (const float*)d_in[0];
    const float* P     = (const float*)d_in[1];
    const float* Wq    = (const float*)d_in[2];
    const float* Wk    = (const float*)d_in[3];
    const float* Wv    = (const float*)d_in[4];
    const float* Wo    = (const float*)d_in[5];
    const float* bo    = (const float*)d_in[6];
    const float* gamma = (const float*)d_in[7];
    const float* beta  = (const float*)d_in[8];
    float* out = (float*)d_out;

    void *pq, *pk, *pv, *pxh, *pxl, *pch, *pcl, *pwh, *pwl;
    cudaGetSymbolAddress(&pq,  g_q);
    cudaGetSymbolAddress(&pk,  g_k);
    cudaGetSymbolAddress(&pv,  g_v);
    cudaGetSymbolAddress(&pxh, g_xh);
    cudaGetSymbolAddress(&pxl, g_xl);
    cudaGetSymbolAddress(&pch, g_ch);
    cudaGetSymbolAddress(&pcl, g_cl);
    cudaGetSymbolAddress(&pwh, g_wh);
    cudaGetSymbolAddress(&pwl, g_wl);

    __nv_bfloat16* wh = (__nv_bfloat16*)pwh;
    __nv_bfloat16* wl = (__nv_bfloat16*)pwl;

    const int dsm = 2 * STAGE_BYTES;                // 110592
    cudaFuncSetAttribute(gemm_mma<0>, cudaFuncAttributeMaxDynamicSharedMemorySize, dsm);
    cudaFuncSetAttribute(gemm_mma<1>, cudaFuncAttributeMaxDynamicSharedMemorySize, dsm);

    // Splits
    dim3 gw(256, 4);
    wsplit_kernel<<<gw, 256>>>(Wq, Wk, Wv, Wo, wh, wl);
    const int nx4 = (int)((size_t)NROW * 512 / 4);
    split_kernel<<<(nx4 + 255) / 256, 256>>>(x, (__nv_bfloat16*)pxh,
                                             (__nv_bfloat16*)pxl, nx4);

    // Fused QKV projection: 12 col tiles over contiguous [Wq;Wk;Wv] rows
    dim3 gq(12, NROW / 128);
    gemm_mma<0><<<gq, 128, dsm>>>((const __nv_bfloat16*)pxh, (const __nv_bfloat16*)pxl,
                                  wh, wl,
                                  (float*)pq, (float*)pk, (float*)pv,
                                  nullptr, nullptr);

    dim3 ga(NSAMP, 2);
    attn_kernel<<<ga, 128>>>(
        (const float*)pq, (const float*)pk, (const float*)pv, P,
        (__nv_bfloat16*)pch, (__nv_bfloat16*)pcl);

    // fc_out + bias + residual
    dim3 go(4, NROW / 128);
    gemm_mma<1><<<go, 128, dsm>>>((const __nv_bfloat16*)pch, (const __nv_bfloat16*)pcl,
                                  wh + 3 * 262144, wl + 3 * 262144,
                                  out, nullptr, nullptr, bo, x);

    ln_kernel<<<NROW / 8, 256>>>(out, gamma, beta);
}

// round 10
// speedup vs baseline: 1.4925x; 1.4925x over previous
#include <cuda_runtime.h>
#include <cuda_bf16.h>
#include <cstdint>

// Problem constants
#define B_  32
#define S_  256
#define D_  17
#define M_  512
#define H_  8
#define DK_ 64
#define NROW  139264          // B*S*D rows of width 512
#define NSAMP 8192            // B*S

// ---------------------------------------------------------------------------
// Scratch (__device__ globals; allocation-free rule)
// ---------------------------------------------------------------------------
__device__ float g_q[(size_t)NROW * M_];
__device__ float g_k[(size_t)NROW * M_];
__device__ float g_v[(size_t)NROW * M_];
__device__ __nv_bfloat16 g_xh[(size_t)NROW * M_];
__device__ __nv_bfloat16 g_xl[(size_t)NROW * M_];
__device__ __nv_bfloat16 g_ch[(size_t)NROW * M_];
__device__ __nv_bfloat16 g_cl[(size_t)NROW * M_];
__device__ __nv_bfloat16 g_wh[4 * 512 * 512];   // Wq,Wk,Wv,Wo hi (rows contiguous)
__device__ __nv_bfloat16 g_wl[4 * 512 * 512];   // lo

// ---------------------------------------------------------------------------
// Helpers
// ---------------------------------------------------------------------------
__device__ __forceinline__ uint32_t smem_u32(const void* p) {
    uint32_t a;
    asm("{ .reg .u64 t; cvta.to.shared.u64 t, %1; cvt.u32.u64 %0, t; }"
        : "=r"(a) : "l"(p));
    return a;
}

__device__ __forceinline__ void cp16(uint32_t dst, const void* src) {
    asm volatile("cp.async.cg.shared.global [%0], [%1], 16;" :: "r"(dst), "l"(src));
}

__device__ __forceinline__ void ldmx4(uint32_t* r, uint32_t addr) {
    asm volatile("ldmatrix.sync.aligned.m8n8.x4.shared.b16 {%0,%1,%2,%3}, [%4];"
                 : "=r"(r[0]), "=r"(r[1]), "=r"(r[2]), "=r"(r[3]) : "r"(addr));
}

__device__ __forceinline__ void mma16816(float* d, const uint32_t* a,
                                         uint32_t b0, uint32_t b1) {
    asm volatile(
        "mma.sync.aligned.m16n8k16.row.col.f32.bf16.bf16.f32 "
        "{%0,%1,%2,%3}, {%4,%5,%6,%7}, {%8,%9}, {%0,%1,%2,%3};"
        : "+f"(d[0]), "+f"(d[1]), "+f"(d[2]), "+f"(d[3])
        : "r"(a[0]), "r"(a[1]), "r"(a[2]), "r"(a[3]), "r"(b0), "r"(b1));
}

// ---------------------------------------------------------------------------
// bf16-split GEMM on HMMA, fused-phase structure (R6 best, unchanged):
//   pass A (iters 0-7):  acc += xh.Wh + xh.Wl   (A LDSM shared by both B's)
//   pass B (iters 8-15): acc += xl.Wh
// BM=BN=128, BK=64 per iter, 128 threads (4 warps 2x2), warp tile 64x64.
// ---------------------------------------------------------------------------
#define ITERS 16
#define ROWB 144
#define STAGE_BYTES (384 * ROWB)    // A(128) + B0(128) + B1(128) rows

__device__ __forceinline__ void load_iter(
    int tid, uint32_t sbase, int r0, int c0, int it,
    const __nv_bfloat16* __restrict__ xh, const __nv_bfloat16* __restrict__ xl,
    const __nv_bfloat16* __restrict__ Wh, const __nv_bfloat16* __restrict__ Wl)
{
    const int kk = (it & 7) * 64;
    const __nv_bfloat16* A = (it < 8) ? xh : xl;
    #pragma unroll
    for (int t = 0; t < 8; t++) {                 // A: 128 rows x 128B
        int f = tid + t * 128;
        int row = f >> 3, ch = f & 7;
        cp16(sbase + row * ROWB + ch * 16, A + ((size_t)(r0 + row) << 9) + kk + ch * 8);
    }
    const uint32_t b0 = sbase + 128 * ROWB;
    #pragma unroll
    for (int t = 0; t < 8; t++) {                 // B0 = Wh
        int f = tid + t * 128;
        int row = f >> 3, ch = f & 7;
        cp16(b0 + row * ROWB + ch * 16, Wh + ((size_t)(c0 + row) << 9) + kk + ch * 8);
    }
    if (it < 8) {
        const uint32_t b1 = sbase + 256 * ROWB;
        #pragma unroll
        for (int t = 0; t < 8; t++) {             // B1 = Wl (pass A only)
            int f = tid + t * 128;
            int row = f >> 3, ch = f & 7;
            cp16(b1 + row * ROWB + ch * 16, Wl + ((size_t)(c0 + row) << 9) + kk + ch * 8);
        }
    }
    asm volatile("cp.async.commit_group;");
}

template<int MODE>
__global__ __launch_bounds__(128)
void gemm_mma(const __nv_bfloat16* __restrict__ Ah,
              const __nv_bfloat16* __restrict__ Al,
              const __nv_bfloat16* __restrict__ Wh,
              const __nv_bfloat16* __restrict__ Wl,
              float* __restrict__ C0, float* __restrict__ C1,
              float* __restrict__ C2,
              const float* __restrict__ bias,
              const float* __restrict__ resid)
{
    extern __shared__ __align__(128) char smem[];

    const int tid = threadIdx.x;
    const int wid = tid >> 5;
    const int lid = tid & 31;
    const int c0 = blockIdx.x << 7;    // col tile (fast dim -> A L2 reuse)
    const int r0 = blockIdx.y << 7;
    const int m0 = (wid & 1) * 64;
    const int n0 = (wid >> 1) * 64;
    const uint32_t sb = smem_u32(smem);

    float acc[4][8][4];
    #pragma unroll
    for (int i = 0; i < 4; i++)
        #pragma unroll
        for (int j = 0; j < 8; j++)
            #pragma unroll
            for (int q = 0; q < 4; q++) acc[i][j][q] = 0.f;

    load_iter(tid, sb, r0, c0, 0, Ah, Al, Wh, Wl);

    const uint32_t a_off = (uint32_t)((m0 + (lid & 15)) * ROWB + ((lid >> 4) << 4));
    const uint32_t b_off = (uint32_t)((n0 + (lid & 7) + ((lid >> 4) << 3)) * ROWB
                                      + (((lid >> 3) & 1) << 4));

    for (int it = 0; it < ITERS; it++) {
        asm volatile("cp.async.wait_group 0;");
        __syncthreads();

        if (it + 1 < ITERS)
            load_iter(tid, sb + ((it + 1) & 1) * STAGE_BYTES, r0, c0, it + 1,
                      Ah, Al, Wh, Wl);

        const uint32_t as  = sb + (it & 1) * STAGE_BYTES;
        const uint32_t bs0 = as + 128 * ROWB;
        const uint32_t bs1 = as + 256 * ROWB;

        #pragma unroll
        for (int kt = 0; kt < 4; kt++) {
            uint32_t a[4][4], b[4][4];
            #pragma unroll
            for (int mi = 0; mi < 4; mi++)
                ldmx4(a[mi], as + a_off + (uint32_t)(mi * 16 * ROWB + kt * 32));
            #pragma unroll
            for (int nj = 0; nj < 4; nj++)
                ldmx4(b[nj], bs0 + b_off + (uint32_t)(nj * 16 * ROWB + kt * 32));
            #pragma unroll
            for (int mi = 0; mi < 4; mi++)
                #pragma unroll
                for (int ni = 0; ni < 8; ni++)
                    mma16816(acc[mi][ni], a[mi],
                             b[ni >> 1][(ni & 1) * 2], b[ni >> 1][(ni & 1) * 2 + 1]);
            if (it < 8) {   // pass A: second B tile (Wl), reuse A fragments
                #pragma unroll
                for (int nj = 0; nj < 4; nj++)
                    ldmx4(b[nj], bs1 + b_off + (uint32_t)(nj * 16 * ROWB + kt * 32));
                #pragma unroll
                for (int mi = 0; mi < 4; mi++)
                    #pragma unroll
                    for (int ni = 0; ni < 8; ni++)
                        mma16816(acc[mi][ni], a[mi],
                                 b[ni >> 1][(ni & 1) * 2], b[ni >> 1][(ni & 1) * 2 + 1]);
            }
        }
    }

    // Epilogue
    float* C;
    int col0;
    if (MODE == 0) {
        const int which = c0 >> 9;
        C = (which == 0) ? C0 : (which == 1) ? C1 : C2;
        col0 = c0 & 511;
    } else {
        C = C0;
        col0 = c0;
    }
    const int g  = lid >> 2;
    const int tg = lid & 3;
    #pragma unroll
    for (int mi = 0; mi < 4; mi++) {
        #pragma unroll
        for (int ni = 0; ni < 8; ni++) {
            const int r = r0 + m0 + mi * 16 + g;
            const int c = col0 + n0 + ni * 8 + tg * 2;
            float2 v0 = make_float2(acc[mi][ni][0], acc[mi][ni][1]);
            float2 v1 = make_float2(acc[mi][ni][2], acc[mi][ni][3]);
            if (MODE == 1) {
                const float2 bb = *(const float2*)(bias + c);
                const float2 q0 = *(const float2*)(resid + ((size_t)r << 9) + c);
                const float2 q1 = *(const float2*)(resid + ((size_t)(r + 8) << 9) + c);
                v0.x += bb.x + q0.x; v0.y += bb.y + q0.y;
                v1.x += bb.x + q1.x; v1.y += bb.y + q1.y;
            }
            *(float2*)(C + ((size_t)r << 9) + c)       = v0;
            *(float2*)(C + ((size_t)(r + 8) << 9) + c) = v1;
        }
    }
}

// ---------------------------------------------------------------------------
// fp32 -> (bf16 hi, bf16 lo) splits
// ---------------------------------------------------------------------------
__global__ __launch_bounds__(256)
void wsplit_kernel(const float* __restrict__ Wq, const float* __restrict__ Wk,
                   const float* __restrict__ Wv, const float* __restrict__ Wo,
                   __nv_bfloat16* __restrict__ hi, __nv_bfloat16* __restrict__ lo)
{
    const int w = blockIdx.y;
    const float* src = (w == 0) ? Wq : (w == 1) ? Wk : (w == 2) ? Wv : Wo;
    const int i = blockIdx.x * 256 + threadIdx.x;      // < 65536
    float4 v = ((const float4*)src)[i];
    __nv_bfloat16 h0 = __float2bfloat16(v.x);
    __nv_bfloat16 h1 = __float2bfloat16(v.y);
    __nv_bfloat16 h2 = __float2bfloat16(v.z);
    __nv_bfloat16 h3 = __float2bfloat16(v.w);
    __nv_bfloat162* hp = (__nv_bfloat162*)(hi + (size_t)w * 262144);
    __nv_bfloat162* lp = (__nv_bfloat162*)(lo + (size_t)w * 262144);
    hp[2 * i]     = __nv_bfloat162(h0, h1);
    hp[2 * i + 1] = __nv_bfloat162(h2, h3);
    lp[2 * i]     = __nv_bfloat162(__float2bfloat16(v.x - __bfloat162float(h0)),
                                   __float2bfloat16(v.y - __bfloat162float(h1)));
    lp[2 * i + 1] = __nv_bfloat162(__float2bfloat16(v.z - __bfloat162float(h2)),
                                   __float2bfloat16(v.w - __bfloat162float(h3)));
}

__global__ __launch_bounds__(256)
void split_kernel(const float* __restrict__ in, __nv_bfloat16* __restrict__ hi,
                  __nv_bfloat16* __restrict__ lo, int n4)
{
    int i = blockIdx.x * 256 + threadIdx.x;
    if (i >= n4) return;
    float4 v = ((const float4*)in)[i];
    __nv_bfloat16 h0 = __float2bfloat16(v.x);
    __nv_bfloat16 h1 = __float2bfloat16(v.y);
    __nv_bfloat16 h2 = __float2bfloat16(v.z);
    __nv_bfloat16 h3 = __float2bfloat16(v.w);
    __nv_bfloat162* hp = (__nv_bfloat162*)hi;
    __nv_bfloat162* lp = (__nv_bfloat162*)lo;
    hp[2 * i]     = __nv_bfloat162(h0, h1);
    hp[2 * i + 1] = __nv_bfloat162(h2, h3);
    lp[2 * i]     = __nv_bfloat162(__float2bfloat16(v.x - __bfloat162float(h0)),
                                   __float2bfloat16(v.y - __bfloat162float(h1)));
    lp[2 * i + 1] = __nv_bfloat162(__float2bfloat16(v.z - __bfloat162float(h2)),
                                   __float2bfloat16(v.w - __bfloat162float(h3)));
}

// ---------------------------------------------------------------------------
// Attention v5: buffer-reuse staging (BUF0 = q then v, BUF1 = k), PADDED
// score writes (R6 semantics, no clamping, no duplicate work).
//   - score blocks d0,e0 in {0,4,8,12,16}; pad rows/cols 17..19 compute
//     garbage from in-array staging bytes and land in the padded 400-stride
//     score region; softmax/ctx consume only rows/cols < 17.
//   - ctx keeps the d<17 store guard.
// smem = 4624 + 4624 + 1600 + 400 = 11248 floats = 45.0KB -> 5 CTAs/SM.
// One CTA per (sample, 4-head group), 128 threads, 4x4 register tiling.
// ---------------------------------------------------------------------------
#define AB0 0
#define AB1 4624
#define ASS 9248                 // 4 heads * 400
#define ASP 10848                // 400
__global__ __launch_bounds__(128)
void attn_kernel(const float* __restrict__ q, const float* __restrict__ k,
                 const float* __restrict__ v, const float* __restrict__ P,
                 __nv_bfloat16* __restrict__ ch, __nv_bfloat16* __restrict__ cl)
{
    __shared__ float sm[11248];  // 44992 bytes
    const int n  = blockIdx.x;
    const int hg = blockIdx.y;
    const int t  = threadIdx.x;
    const size_t base = (size_t)n * D_ * M_;

    // Phase 1: stage q -> BUF0, k -> BUF1 ([h][d][c], row stride 68)
    for (int f = t; f < 1088; f += 128) {
        int d = f >> 6, hc = f & 63;
        int h = hc >> 4, c4 = hc & 15;
        size_t goff = base + (size_t)d * 512 + (hg * 4 + h) * 64 + c4 * 4;
        int soff = (h * 17 + d) * 68 + c4 * 4;
        *(float4*)(sm + AB0 + soff) = *(const float4*)(q + goff);
        *(float4*)(sm + AB1 + soff) = *(const float4*)(k + goff);
    }
    for (int f = t; f < 289; f += 128)
        sm[ASP + (f / 17) * 20 + (f % 17)] = P[f];
    __syncthreads();

    // Phase 2: scores, 4 heads x 25 blocks of 4x4 = 100 tasks (padded blocks;
    // pad reads stay inside sm[], pad writes land in the 400-stride pad area)
    if (t < 100) {
        const int h = t / 25, blk = t % 25;
        const int d0 = (blk / 5) * 4, e0 = (blk % 5) * 4;
        const float* sq = sm + AB0 + (h * 17 + d0) * 68;
        const float* sk = sm + AB1 + (h * 17 + e0) * 68;
        float acc[4][4];
        #pragma unroll
        for (int i = 0; i < 4; i++)
            #pragma unroll
            for (int j = 0; j < 4; j++) acc[i][j] = 0.f;
        #pragma unroll 4
        for (int c4 = 0; c4 < 16; c4++) {
            float4 qa[4], kb[4];
            #pragma unroll
            for (int i = 0; i < 4; i++) qa[i] = *(const float4*)(sq + i * 68 + c4 * 4);
            #pragma unroll
            for (int j = 0; j < 4; j++) kb[j] = *(const float4*)(sk + j * 68 + c4 * 4);
            #pragma unroll
            for (int i = 0; i < 4; i++)
                #pragma unroll
                for (int j = 0; j < 4; j++)
                    acc[i][j] += qa[i].x * kb[j].x + qa[i].y * kb[j].y
                               + qa[i].z * kb[j].z + qa[i].w * kb[j].w;
        }
        float* ss = sm + ASS + h * 400;
        #pragma unroll
        for (int i = 0; i < 4; i++)
            #pragma unroll
            for (int j = 0; j < 4; j++)
                ss[(d0 + i) * 20 + e0 + j] =
                    acc[i][j] * 0.125f + sm[ASP + (d0 + i) * 20 + e0 + j];
    }
    __syncthreads();

    // Phase 3: stage v into BUF0 (q no longer needed) + softmax on ss
    for (int f = t; f < 1088; f += 128) {
        int d = f >> 6, hc = f & 63;
        int h = hc >> 4, c4 = hc & 15;
        size_t goff = base + (size_t)d * 512 + (hg * 4 + h) * 64 + c4 * 4;
        *(float4*)(sm + AB0 + (h * 17 + d) * 68 + c4 * 4) = *(const float4*)(v + goff);
    }
    if (t < 68) {
        float* row = sm + ASS + (t / 17) * 400 + (t % 17) * 20;
        float mx = -1e30f;
        #pragma unroll
        for (int e = 0; e < 17; e++) mx = fmaxf(mx, row[e]);
        float sum = 0.f;
        #pragma unroll
        for (int e = 0; e < 17; e++) {
            float ex = __expf(row[e] - mx);
            row[e] = ex;
            sum += ex;
        }
        float inv = 1.f / sum;
        #pragma unroll
        for (int e = 0; e < 17; e++) row[e] *= inv;
    }
    __syncthreads();

    // Phase 4: ctx, 4 heads x (5 dblk x 16 cblk) = 320 tasks -> bf16 hi/lo.
    // Pad rows (d >= 17) compute garbage, store guarded by d < 17.
    for (int task = t; task < 320; task += 128) {
        const int h = task / 80, rem = task % 80;
        const int d0 = (rem / 16) * 4, c0c = (rem % 16) * 4;
        const float* ss = sm + ASS + h * 400;
        const float* sv = sm + AB0 + h * 17 * 68 + c0c;
        float acc[4][4];
        #pragma unroll
        for (int i = 0; i < 4; i++)
            #pragma unroll
            for (int j = 0; j < 4; j++) acc[i][j] = 0.f;
        #pragma unroll 1
        for (int e = 0; e < 17; e++) {
            const float4 vv = *(const float4*)(sv + e * 68);
            #pragma unroll
            for (int i = 0; i < 4; i++) {
                const float w = ss[(d0 + i) * 20 + e];
                acc[i][0] += w * vv.x;
                acc[i][1] += w * vv.y;
                acc[i][2] += w * vv.z;
                acc[i][3] += w * vv.w;
            }
        }
        #pragma unroll
        for (int i = 0; i < 4; i++) {
            const int d = d0 + i;
            if (d < 17) {
                const size_t off = base + (size_t)d * 512 + (hg * 4 + h) * 64 + c0c;
                __nv_bfloat16 hh[4], ll[4];
                #pragma unroll
                for (int j = 0; j < 4; j++) {
                    hh[j] = __float2bfloat16(acc[i][j]);
                    ll[j] = __float2bfloat16(acc[i][j] - __bfloat162float(hh[j]));
                }
                *(uint2*)(ch + off) = *(uint2*)hh;
                *(uint2*)(cl + off) = *(uint2*)ll;
            }
        }
    }
}

// ---------------------------------------------------------------------------
// In-place LayerNorm (warp per row, width 512), eps = 1e-5
// ---------------------------------------------------------------------------
__global__ __launch_bounds__(256)
void ln_kernel(float* __restrict__ out, const float* __restrict__ gamma,
               const float* __restrict__ beta)
{
    const int row  = blockIdx.x * 8 + (threadIdx.x >> 5);
    const int lane = threadIdx.x & 31;
    const size_t base = (size_t)row * 512;

    float4 vals[4];
    float sum = 0.f, sq = 0.f;
    #pragma unroll
    for (int j = 0; j < 4; j++) {
        vals[j] = *(const float4*)(out + base + (size_t)(j * 32 + lane) * 4);
        sum += vals[j].x + vals[j].y + vals[j].z + vals[j].w;
        sq  += vals[j].x * vals[j].x + vals[j].y * vals[j].y
             + vals[j].z * vals[j].z + vals[j].w * vals[j].w;
    }
    #pragma unroll
    for (int o = 16; o > 0; o >>= 1) {
        sum += __shfl_xor_sync(0xffffffffu, sum, o);
        sq  += __shfl_xor_sync(0xffffffffu, sq,  o);
    }
    const float mean = sum * (1.f / 512.f);
    const float var  = sq * (1.f / 512.f) - mean * mean;
    const float rstd = rsqrtf(var + 1e-5f);

    #pragma unroll
    for (int j = 0; j < 4; j++) {
        int c = (j * 32 + lane) * 4;
        float4 g  = *(const float4*)(gamma + c);
        float4 bb = *(const float4*)(beta + c);
        float4 v;
        v.x = (vals[j].x - mean) * rstd * g.x + bb.x;
        v.y = (vals[j].y - mean) * rstd * g.y + bb.y;
        v.z = (vals[j].z - mean) * rstd * g.z + bb.z;
        v.w = (vals[j].w - mean) * rstd * g.w + bb.w;
        *(float4*)(out + base + c) = v;
    }
}

// ---------------------------------------------------------------------------
extern "C" void kernel_launch(void* const* d_in, const int* in_sizes, int n_in,
                              void* d_out, int out_size)
{
    const float* x     = (const float*)d_in[0];
    const float* P     = (const float*)d_in[1];
    const float* Wq    = (const float*)d_in[2];
    const float* Wk    = (const float*)d_in[3];
    const float* Wv    = (const float*)d_in[4];
    const float* Wo    = (const float*)d_in[5];
    const float* bo    = (const float*)d_in[6];
    const float* gamma = (const float*)d_in[7];
    const float* beta  = (const float*)d_in[8];
    float* out = (float*)d_out;

    void *pq, *pk, *pv, *pxh, *pxl, *pch, *pcl, *pwh, *pwl;
    cudaGetSymbolAddress(&pq,  g_q);
    cudaGetSymbolAddress(&pk,  g_k);
    cudaGetSymbolAddress(&pv,  g_v);
    cudaGetSymbolAddress(&pxh, g_xh);
    cudaGetSymbolAddress(&pxl, g_xl);
    cudaGetSymbolAddress(&pch, g_ch);
    cudaGetSymbolAddress(&pcl, g_cl);
    cudaGetSymbolAddress(&pwh, g_wh);
    cudaGetSymbolAddress(&pwl, g_wl);

    __nv_bfloat16* wh = (__nv_bfloat16*)pwh;
    __nv_bfloat16* wl = (__nv_bfloat16*)pwl;

    const int dsm = 2 * STAGE_BYTES;                // 110592
    cudaFuncSetAttribute(gemm_mma<0>, cudaFuncAttributeMaxDynamicSharedMemorySize, dsm);
    cudaFuncSetAttribute(gemm_mma<1>, cudaFuncAttributeMaxDynamicSharedMemorySize, dsm);

    // Splits
    dim3 gw(256, 4);
    wsplit_kernel<<<gw, 256>>>(Wq, Wk, Wv, Wo, wh, wl);
    const int nx4 = (int)((size_t)NROW * 512 / 4);
    split_kernel<<<(nx4 + 255) / 256, 256>>>(x, (__nv_bfloat16*)pxh,
                                             (__nv_bfloat16*)pxl, nx4);

    // Fused QKV projection: 12 col tiles over contiguous [Wq;Wk;Wv] rows
    dim3 gq(12, NROW / 128);
    gemm_mma<0><<<gq, 128, dsm>>>((const __nv_bfloat16*)pxh, (const __nv_bfloat16*)pxl,
                                  wh, wl,
                                  (float*)pq, (float*)pk, (float*)pv,
                                  nullptr, nullptr);

    dim3 ga(NSAMP, 2);
    attn_kernel<<<ga, 128>>>(
        (const float*)pq, (const float*)pk, (const float*)pv, P,
        (__nv_bfloat16*)pch, (__nv_bfloat16*)pcl);

    // fc_out + bias + residual
    dim3 go(4, NROW / 128);
    gemm_mma<1><<<go, 128, dsm>>>((const __nv_bfloat16*)pch, (const __nv_bfloat16*)pcl,
                                  wh + 3 * 262144, wl + 3 * 262144,
                                  out, nullptr, nullptr, bo, x);

    ln_kernel<<<NROW / 8, 256>>>(out, gamma, beta);
}